// round 1
// baseline (speedup 1.0000x reference)
#include <cuda_runtime.h>
#include <cuda_bf16.h>
#include <cstdint>

// Problem constants (fixed by the reference)
#define NUM_USERS  100000
#define NUM_ITEMS  50000
#define NUM_BRANDS 1000
#define NTOT       (NUM_USERS + NUM_ITEMS + NUM_BRANDS)   // 151000
#define DIM        64
#define DCONT      384
#define KDIM       (DIM + DCONT)                          // 448
#define NDF        (NTOT * DIM)                           // 9,664,000 floats
#define ND4        (NDF / 4)                              // 2,416,000 float4
#define UD4        (NUM_USERS * DIM / 4)                  // 1,600,000
#define ITEM_END4  ((NUM_USERS + NUM_ITEMS) * DIM / 4)    // 2,400,000
#define ID4        (NUM_ITEMS * DIM / 4)                  // 800,000
#define OUT4       (ND4 + UD4 + ID4)                      // 4,816,000 float4

// Scratch: 3 node-feature buffers (38.66 MB each). __device__ globals are the
// sanctioned no-alloc scratch mechanism.
__device__ float g_bufA[NDF];
__device__ float g_bufB[NDF];
__device__ float g_acc [NDF];

// ---------------------------------------------------------------------------
// Kernel 1: fused_item = leaky_relu([item_id | item_content] @ W^T + b)
// Tiled fp32 GEMM: BM=64 rows, BN=64 (all outputs), BK=16, 256 threads,
// 4x4 register tile per thread. Writes directly into bufA item segment.
// ---------------------------------------------------------------------------
__global__ void fuse_gemm_kernel(const float* __restrict__ id_emb,
                                 const float* __restrict__ content,
                                 const float* __restrict__ W,
                                 const float* __restrict__ bias,
                                 float* __restrict__ out) {
    __shared__ float As[16][65];  // [k][row]
    __shared__ float Ws[16][65];  // [k][out_col]

    const int block_row = blockIdx.x * 64;
    const int tid = threadIdx.x;           // 0..255
    const int tx = tid & 15;                // col group (16 groups of 4)
    const int ty = tid >> 4;                // row group (16 groups of 4)

    float acc[4][4];
#pragma unroll
    for (int i = 0; i < 4; i++)
#pragma unroll
        for (int j = 0; j < 4; j++) acc[i][j] = 0.f;

    for (int k0 = 0; k0 < KDIM; k0 += 16) {
        // Load A tile (64 rows x 16 k), transposed into As[k][r]
#pragma unroll
        for (int i = 0; i < 4; i++) {
            int idx = tid + i * 256;
            int r = idx >> 4;
            int k = idx & 15;
            int gr = block_row + r;
            int gk = k0 + k;
            float v = 0.f;
            if (gr < NUM_ITEMS) {
                v = (gk < DIM) ? id_emb[gr * DIM + gk]
                               : content[gr * DCONT + (gk - DIM)];
            }
            As[k][r] = v;
        }
        // Load W tile (64 out x 16 k), transposed into Ws[k][j]
#pragma unroll
        for (int i = 0; i < 4; i++) {
            int idx = tid + i * 256;
            int j = idx >> 4;
            int k = idx & 15;
            Ws[k][j] = W[j * KDIM + k0 + k];
        }
        __syncthreads();

#pragma unroll
        for (int k = 0; k < 16; k++) {
            float a[4], w[4];
#pragma unroll
            for (int i = 0; i < 4; i++) a[i] = As[k][ty * 4 + i];
#pragma unroll
            for (int j = 0; j < 4; j++) w[j] = Ws[k][tx * 4 + j];
#pragma unroll
            for (int i = 0; i < 4; i++)
#pragma unroll
                for (int j = 0; j < 4; j++) acc[i][j] += a[i] * w[j];
        }
        __syncthreads();
    }

#pragma unroll
    for (int i = 0; i < 4; i++) {
        int gr = block_row + ty * 4 + i;
        if (gr >= NUM_ITEMS) continue;
#pragma unroll
        for (int j = 0; j < 4; j++) {
            int jj = tx * 4 + j;
            float v = acc[i][j] + bias[jj];
            out[gr * DIM + jj] = (v > 0.f) ? v : 0.01f * v;
        }
    }
}

// ---------------------------------------------------------------------------
// Kernel 2: assemble ego into bufA (user + brand segments; item segment was
// written by the GEMM), copy to acc, zero bufB.
// ---------------------------------------------------------------------------
__global__ void init_kernel(float4* __restrict__ A4,
                            float4* __restrict__ B4,
                            float4* __restrict__ acc4,
                            const float4* __restrict__ user4,
                            const float4* __restrict__ brand4) {
    int idx = blockIdx.x * blockDim.x + threadIdx.x;
    if (idx >= ND4) return;
    float4 v;
    if (idx < UD4)            v = user4[idx];
    else if (idx < ITEM_END4) v = A4[idx];            // GEMM output (in place)
    else                      v = brand4[idx - ITEM_END4];
    A4[idx]   = v;
    acc4[idx] = v;
    B4[idx]   = make_float4(0.f, 0.f, 0.f, 0.f);
}

// ---------------------------------------------------------------------------
// Kernel 3: SpMM — y[row] += val * x[col] per edge.
// 16 lanes per edge; each lane handles one float4 slice of the 64-dim row.
// Vectorized reduction: red.global.add.v4.f32 (sm_90+).
// ---------------------------------------------------------------------------
__global__ void spmm_kernel(const int*   __restrict__ rows,
                            const int*   __restrict__ cols,
                            const float* __restrict__ vals,
                            const float* __restrict__ x,
                            float*       __restrict__ y,
                            int E) {
    long long t = (long long)blockIdx.x * blockDim.x + threadIdx.x;
    int e = (int)(t >> 4);
    if (e >= E) return;
    int sub = (int)(t & 15);

    int   r = __ldg(rows + e);
    int   c = __ldg(cols + e);
    float v = __ldg(vals + e);

    const float4* xp = reinterpret_cast<const float4*>(x + (size_t)c * DIM) + sub;
    float4 xv = __ldg(xp);

    float* yp = y + (size_t)r * DIM + sub * 4;
    asm volatile("red.global.add.v4.f32 [%0], {%1, %2, %3, %4};"
                 :: "l"(yp), "f"(xv.x * v), "f"(xv.y * v),
                    "f"(xv.z * v), "f"(xv.w * v)
                 : "memory");
}

// ---------------------------------------------------------------------------
// Kernel 4: acc += layer_out; zero the buffer that becomes the next target.
// ---------------------------------------------------------------------------
__global__ void add_zero_kernel(float4* __restrict__ acc4,
                                const float4* __restrict__ lo4,
                                float4* __restrict__ z4) {
    int idx = blockIdx.x * blockDim.x + threadIdx.x;
    if (idx >= ND4) return;
    float4 a = acc4[idx];
    float4 l = lo4[idx];
    a.x += l.x; a.y += l.y; a.z += l.z; a.w += l.w;
    acc4[idx] = a;
    z4[idx]   = make_float4(0.f, 0.f, 0.f, 0.f);
}

// ---------------------------------------------------------------------------
// Kernel 5: finalize — out = [acc/4 (user|item|brand contiguous), user_emb,
// item_id_emb]
// ---------------------------------------------------------------------------
__global__ void finalize_kernel(float4* __restrict__ out4,
                                const float4* __restrict__ acc4,
                                const float4* __restrict__ user4,
                                const float4* __restrict__ itemid4) {
    int idx = blockIdx.x * blockDim.x + threadIdx.x;
    if (idx >= OUT4) return;
    float4 v;
    if (idx < ND4) {
        v = acc4[idx];
        v.x *= 0.25f; v.y *= 0.25f; v.z *= 0.25f; v.w *= 0.25f;
    } else if (idx < ND4 + UD4) {
        v = user4[idx - ND4];
    } else {
        v = itemid4[idx - (ND4 + UD4)];
    }
    out4[idx] = v;
}

// ---------------------------------------------------------------------------
extern "C" void kernel_launch(void* const* d_in, const int* in_sizes, int n_in,
                              void* d_out, int out_size) {
    const int*   edge_row = (const int*)  d_in[0];
    const int*   edge_col = (const int*)  d_in[1];
    const float* edge_val = (const float*)d_in[2];
    const float* user_emb = (const float*)d_in[3];
    const float* item_id  = (const float*)d_in[4];
    const float* brand    = (const float*)d_in[5];
    const float* content  = (const float*)d_in[6];
    const float* fusion_W = (const float*)d_in[7];
    const float* fusion_b = (const float*)d_in[8];
    const int E = in_sizes[0];

    float *A, *B, *acc;
    cudaGetSymbolAddress((void**)&A,   g_bufA);
    cudaGetSymbolAddress((void**)&B,   g_bufB);
    cudaGetSymbolAddress((void**)&acc, g_acc);

    // 1) fused item GEMM -> item segment of bufA
    fuse_gemm_kernel<<<(NUM_ITEMS + 63) / 64, 256>>>(
        item_id, content, fusion_W, fusion_b, A + (size_t)NUM_USERS * DIM);

    // 2) assemble ego / acc, zero B
    init_kernel<<<(ND4 + 255) / 256, 256>>>(
        (float4*)A, (float4*)B, (float4*)acc,
        (const float4*)user_emb, (const float4*)brand);

    // 3) three propagation layers
    float* src = A;
    float* dst = B;
    long long spmm_threads = (long long)E * 16;
    int spmm_blocks = (int)((spmm_threads + 255) / 256);
    for (int l = 0; l < 3; l++) {
        spmm_kernel<<<spmm_blocks, 256>>>(edge_row, edge_col, edge_val,
                                          src, dst, E);
        add_zero_kernel<<<(ND4 + 255) / 256, 256>>>(
            (float4*)acc, (const float4*)dst, (float4*)src);
        float* tmp = src; src = dst; dst = tmp;
    }

    // 4) finalize output
    finalize_kernel<<<(OUT4 + 255) / 256, 256>>>(
        (float4*)d_out, (const float4*)acc,
        (const float4*)user_emb, (const float4*)item_id);
}

// round 2
// speedup vs baseline: 1.7677x; 1.7677x over previous
#include <cuda_runtime.h>
#include <cuda_bf16.h>
#include <cstdint>

#define NUM_USERS  100000
#define NUM_ITEMS  50000
#define NUM_BRANDS 1000
#define NTOT       (NUM_USERS + NUM_ITEMS + NUM_BRANDS)   // 151000
#define DIM        64
#define DCONT      384
#define KDIM       (DIM + DCONT)                          // 448
#define NDF        (NTOT * DIM)                           // 9,664,000 floats
#define ND4        (NDF / 4)
#define UD4        (NUM_USERS * DIM / 4)
#define ITEM_END4  ((NUM_USERS + NUM_ITEMS) * DIM / 4)
#define EMAX       4800000
#define SCAN_CHUNK 1024
#define SCAN_NBLK  ((NTOT + SCAN_CHUNK - 1) / SCAN_CHUNK)  // 148

// Scratch (device globals = sanctioned no-alloc scratch)
__device__ float g_bufA[NDF];
__device__ float g_bufB[NDF];
__device__ float g_acc [NDF];
__device__ int   g_rowptr[NTOT + 1];
__device__ int   g_cursor[NTOT];          // doubles as histogram counts
__device__ int   g_cols[EMAX];
__device__ float g_vals[EMAX];
__device__ int   g_bsum[SCAN_NBLK];
__device__ int   g_boff[SCAN_NBLK];

// ---------------------------------------------------------------------------
// 1) fused_item = leaky_relu([item_id | item_content] @ W^T + b)
// ---------------------------------------------------------------------------
__global__ void fuse_gemm_kernel(const float* __restrict__ id_emb,
                                 const float* __restrict__ content,
                                 const float* __restrict__ W,
                                 const float* __restrict__ bias,
                                 float* __restrict__ out) {
    __shared__ float As[16][65];
    __shared__ float Ws[16][65];

    const int block_row = blockIdx.x * 64;
    const int tid = threadIdx.x;
    const int tx = tid & 15;
    const int ty = tid >> 4;

    float acc[4][4];
#pragma unroll
    for (int i = 0; i < 4; i++)
#pragma unroll
        for (int j = 0; j < 4; j++) acc[i][j] = 0.f;

    for (int k0 = 0; k0 < KDIM; k0 += 16) {
#pragma unroll
        for (int i = 0; i < 4; i++) {
            int idx = tid + i * 256;
            int r = idx >> 4, k = idx & 15;
            int gr = block_row + r, gk = k0 + k;
            float v = 0.f;
            if (gr < NUM_ITEMS)
                v = (gk < DIM) ? id_emb[gr * DIM + gk]
                               : content[gr * DCONT + (gk - DIM)];
            As[k][r] = v;
        }
#pragma unroll
        for (int i = 0; i < 4; i++) {
            int idx = tid + i * 256;
            int j = idx >> 4, k = idx & 15;
            Ws[k][j] = W[j * KDIM + k0 + k];
        }
        __syncthreads();
#pragma unroll
        for (int k = 0; k < 16; k++) {
            float a[4], w[4];
#pragma unroll
            for (int i = 0; i < 4; i++) a[i] = As[k][ty * 4 + i];
#pragma unroll
            for (int j = 0; j < 4; j++) w[j] = Ws[k][tx * 4 + j];
#pragma unroll
            for (int i = 0; i < 4; i++)
#pragma unroll
                for (int j = 0; j < 4; j++) acc[i][j] += a[i] * w[j];
        }
        __syncthreads();
    }
#pragma unroll
    for (int i = 0; i < 4; i++) {
        int gr = block_row + ty * 4 + i;
        if (gr >= NUM_ITEMS) continue;
#pragma unroll
        for (int j = 0; j < 4; j++) {
            int jj = tx * 4 + j;
            float v = acc[i][j] + bias[jj];
            out[gr * DIM + jj] = (v > 0.f) ? v : 0.01f * v;
        }
    }
}

// ---------------------------------------------------------------------------
// 2) assemble ego into bufA, copy to acc. (No zeroing needed anymore.)
// ---------------------------------------------------------------------------
__global__ void init_kernel(float4* __restrict__ A4,
                            float4* __restrict__ acc4,
                            const float4* __restrict__ user4,
                            const float4* __restrict__ brand4) {
    int idx = blockIdx.x * blockDim.x + threadIdx.x;
    if (idx >= ND4) return;
    float4 v;
    if (idx < UD4)            v = user4[idx];
    else if (idx < ITEM_END4) v = A4[idx];
    else                      v = brand4[idx - ITEM_END4];
    A4[idx]   = v;
    acc4[idx] = v;
}

// ---------------------------------------------------------------------------
// CSR build: histogram -> 2-level exclusive scan -> scatter
// ---------------------------------------------------------------------------
__global__ void hist_kernel(const int* __restrict__ rows, int E,
                            int* __restrict__ cnt) {
    int i = blockIdx.x * blockDim.x + threadIdx.x;
    if (i < E) atomicAdd(&cnt[rows[i]], 1);
}

__global__ void scan_partial_kernel(const int* __restrict__ cnt,
                                    int* __restrict__ bsum) {
    __shared__ int s[256];
    int b = blockIdx.x, t = threadIdx.x;
    int base = b * SCAN_CHUNK + t * 4;
    int v = 0;
#pragma unroll
    for (int j = 0; j < 4; j++) {
        int idx = base + j;
        if (idx < NTOT) v += cnt[idx];
    }
    s[t] = v;
    __syncthreads();
    for (int off = 128; off > 0; off >>= 1) {
        if (t < off) s[t] += s[t + off];
        __syncthreads();
    }
    if (t == 0) bsum[b] = s[0];
}

__global__ void scan_bsum_kernel(const int* __restrict__ bsum,
                                 int* __restrict__ boff) {
    __shared__ int s[256];
    int t = threadIdx.x;
    int v = (t < SCAN_NBLK) ? bsum[t] : 0;
    s[t] = v;
    __syncthreads();
    for (int off = 1; off < 256; off <<= 1) {
        int tmp = (t >= off) ? s[t - off] : 0;
        __syncthreads();
        s[t] += tmp;
        __syncthreads();
    }
    if (t < SCAN_NBLK) boff[t] = s[t] - v;  // exclusive
}

__global__ void write_rowptr_kernel(const int* __restrict__ cnt,
                                    const int* __restrict__ boff,
                                    int* __restrict__ rp,
                                    int* __restrict__ cur, int E) {
    __shared__ int s[256];
    int b = blockIdx.x, t = threadIdx.x;
    int base = b * SCAN_CHUNK + t * 4;
    int loc[4];
    int v = 0;
#pragma unroll
    for (int j = 0; j < 4; j++) {
        int idx = base + j;
        loc[j] = (idx < NTOT) ? cnt[idx] : 0;
        v += loc[j];
    }
    s[t] = v;
    __syncthreads();
    for (int off = 1; off < 256; off <<= 1) {
        int tmp = (t >= off) ? s[t - off] : 0;
        __syncthreads();
        s[t] += tmp;
        __syncthreads();
    }
    int run = s[t] - v + boff[b];
#pragma unroll
    for (int j = 0; j < 4; j++) {
        int idx = base + j;
        if (idx < NTOT) { rp[idx] = run; cur[idx] = run; }
        run += loc[j];
    }
    if (b == 0 && t == 0) rp[NTOT] = E;
}

__global__ void scatter_kernel(const int* __restrict__ rows,
                               const int* __restrict__ cols,
                               const float* __restrict__ vals, int E,
                               int* __restrict__ cur,
                               int* __restrict__ cs,
                               float* __restrict__ vs) {
    int i = blockIdx.x * blockDim.x + threadIdx.x;
    if (i >= E) return;
    int r = rows[i];
    int p = atomicAdd(&cur[r], 1);
    cs[p] = cols[i];
    vs[p] = vals[i];
}

// ---------------------------------------------------------------------------
// CSR SpMM, warp-per-row, float2 per lane. Mid layers: y=res, acc+=res.
// ---------------------------------------------------------------------------
__global__ void spmm_mid_kernel(const int* __restrict__ rp,
                                const int* __restrict__ cs,
                                const float* __restrict__ vs,
                                const float* __restrict__ x,
                                float* __restrict__ y,
                                float* __restrict__ acc) {
    int g = blockIdx.x * blockDim.x + threadIdx.x;
    int row = g >> 5;
    int lane = g & 31;
    if (row >= NTOT) return;
    int s = __ldg(rp + row), e = __ldg(rp + row + 1);
    const float2* X = reinterpret_cast<const float2*>(x);
    float ax = 0.f, ay = 0.f;
    int i = s;
    for (; i + 4 <= e; i += 4) {
        int c0 = __ldg(cs + i),     c1 = __ldg(cs + i + 1);
        int c2 = __ldg(cs + i + 2), c3 = __ldg(cs + i + 3);
        float v0 = __ldg(vs + i),     v1 = __ldg(vs + i + 1);
        float v2 = __ldg(vs + i + 2), v3 = __ldg(vs + i + 3);
        float2 x0 = __ldg(X + (size_t)c0 * 32 + lane);
        float2 x1 = __ldg(X + (size_t)c1 * 32 + lane);
        float2 x2 = __ldg(X + (size_t)c2 * 32 + lane);
        float2 x3 = __ldg(X + (size_t)c3 * 32 + lane);
        ax = fmaf(v0, x0.x, ax); ay = fmaf(v0, x0.y, ay);
        ax = fmaf(v1, x1.x, ax); ay = fmaf(v1, x1.y, ay);
        ax = fmaf(v2, x2.x, ax); ay = fmaf(v2, x2.y, ay);
        ax = fmaf(v3, x3.x, ax); ay = fmaf(v3, x3.y, ay);
    }
    for (; i < e; i++) {
        int c = __ldg(cs + i);
        float v = __ldg(vs + i);
        float2 xv = __ldg(X + (size_t)c * 32 + lane);
        ax = fmaf(v, xv.x, ax); ay = fmaf(v, xv.y, ay);
    }
    size_t o = (size_t)row * 32 + lane;
    reinterpret_cast<float2*>(y)[o] = make_float2(ax, ay);
    float2* A = reinterpret_cast<float2*>(acc);
    float2 a = A[o];
    a.x += ax; a.y += ay;
    A[o] = a;
}

// Last layer: out = (acc + res) * 0.25, written straight into d_out.
__global__ void spmm_last_kernel(const int* __restrict__ rp,
                                 const int* __restrict__ cs,
                                 const float* __restrict__ vs,
                                 const float* __restrict__ x,
                                 const float* __restrict__ acc,
                                 float* __restrict__ out) {
    int g = blockIdx.x * blockDim.x + threadIdx.x;
    int row = g >> 5;
    int lane = g & 31;
    if (row >= NTOT) return;
    int s = __ldg(rp + row), e = __ldg(rp + row + 1);
    const float2* X = reinterpret_cast<const float2*>(x);
    float ax = 0.f, ay = 0.f;
    int i = s;
    for (; i + 4 <= e; i += 4) {
        int c0 = __ldg(cs + i),     c1 = __ldg(cs + i + 1);
        int c2 = __ldg(cs + i + 2), c3 = __ldg(cs + i + 3);
        float v0 = __ldg(vs + i),     v1 = __ldg(vs + i + 1);
        float v2 = __ldg(vs + i + 2), v3 = __ldg(vs + i + 3);
        float2 x0 = __ldg(X + (size_t)c0 * 32 + lane);
        float2 x1 = __ldg(X + (size_t)c1 * 32 + lane);
        float2 x2 = __ldg(X + (size_t)c2 * 32 + lane);
        float2 x3 = __ldg(X + (size_t)c3 * 32 + lane);
        ax = fmaf(v0, x0.x, ax); ay = fmaf(v0, x0.y, ay);
        ax = fmaf(v1, x1.x, ax); ay = fmaf(v1, x1.y, ay);
        ax = fmaf(v2, x2.x, ax); ay = fmaf(v2, x2.y, ay);
        ax = fmaf(v3, x3.x, ax); ay = fmaf(v3, x3.y, ay);
    }
    for (; i < e; i++) {
        int c = __ldg(cs + i);
        float v = __ldg(vs + i);
        float2 xv = __ldg(X + (size_t)c * 32 + lane);
        ax = fmaf(v, xv.x, ax); ay = fmaf(v, xv.y, ay);
    }
    size_t o = (size_t)row * 32 + lane;
    float2 a = reinterpret_cast<const float2*>(acc)[o];
    reinterpret_cast<float2*>(out)[o] =
        make_float2((a.x + ax) * 0.25f, (a.y + ay) * 0.25f);
}

// ---------------------------------------------------------------------------
extern "C" void kernel_launch(void* const* d_in, const int* in_sizes, int n_in,
                              void* d_out, int out_size) {
    const int*   edge_row = (const int*)  d_in[0];
    const int*   edge_col = (const int*)  d_in[1];
    const float* edge_val = (const float*)d_in[2];
    const float* user_emb = (const float*)d_in[3];
    const float* item_id  = (const float*)d_in[4];
    const float* brand    = (const float*)d_in[5];
    const float* content  = (const float*)d_in[6];
    const float* fusion_W = (const float*)d_in[7];
    const float* fusion_b = (const float*)d_in[8];
    const int E = in_sizes[0];

    float *A, *B, *acc, *vals_s;
    int *rp, *cur, *cols_s, *bsum, *boff;
    cudaGetSymbolAddress((void**)&A,      g_bufA);
    cudaGetSymbolAddress((void**)&B,      g_bufB);
    cudaGetSymbolAddress((void**)&acc,    g_acc);
    cudaGetSymbolAddress((void**)&rp,     g_rowptr);
    cudaGetSymbolAddress((void**)&cur,    g_cursor);
    cudaGetSymbolAddress((void**)&cols_s, g_cols);
    cudaGetSymbolAddress((void**)&vals_s, g_vals);
    cudaGetSymbolAddress((void**)&bsum,   g_bsum);
    cudaGetSymbolAddress((void**)&boff,   g_boff);

    // CSR build
    cudaMemsetAsync(cur, 0, NTOT * sizeof(int));
    hist_kernel<<<(E + 255) / 256, 256>>>(edge_row, E, cur);
    scan_partial_kernel<<<SCAN_NBLK, 256>>>(cur, bsum);
    scan_bsum_kernel<<<1, 256>>>(bsum, boff);
    write_rowptr_kernel<<<SCAN_NBLK, 256>>>(cur, boff, rp, cur, E);
    scatter_kernel<<<(E + 255) / 256, 256>>>(edge_row, edge_col, edge_val, E,
                                             cur, cols_s, vals_s);

    // Fused item GEMM + ego assembly
    fuse_gemm_kernel<<<(NUM_ITEMS + 63) / 64, 256>>>(
        item_id, content, fusion_W, fusion_b, A + (size_t)NUM_USERS * DIM);
    init_kernel<<<(ND4 + 255) / 256, 256>>>(
        (float4*)A, (float4*)acc, (const float4*)user_emb,
        (const float4*)brand);

    // Propagation
    int spmm_blocks = (NTOT * 32 + 255) / 256;
    spmm_mid_kernel<<<spmm_blocks, 256>>>(rp, cols_s, vals_s, A, B, acc);
    spmm_mid_kernel<<<spmm_blocks, 256>>>(rp, cols_s, vals_s, B, A, acc);
    spmm_last_kernel<<<spmm_blocks, 256>>>(rp, cols_s, vals_s, A, acc,
                                           (float*)d_out);

    // Echo tensors
    cudaMemcpyAsync((float*)d_out + NDF, user_emb,
                    (size_t)NUM_USERS * DIM * sizeof(float),
                    cudaMemcpyDeviceToDevice);
    cudaMemcpyAsync((float*)d_out + NDF + NUM_USERS * DIM, item_id,
                    (size_t)NUM_ITEMS * DIM * sizeof(float),
                    cudaMemcpyDeviceToDevice);
}

// round 3
// speedup vs baseline: 2.2040x; 1.2468x over previous
#include <cuda_runtime.h>
#include <cuda_bf16.h>
#include <cstdint>

#define NUM_USERS  100000
#define NUM_ITEMS  50000
#define NUM_BRANDS 1000
#define NTOT       (NUM_USERS + NUM_ITEMS + NUM_BRANDS)   // 151000
#define DIM        64
#define DCONT      384
#define KDIM       (DIM + DCONT)                          // 448
#define NDF        (NTOT * DIM)
#define ND4        (NDF / 4)
#define UD4        (NUM_USERS * DIM / 4)                  // 1,600,000
#define ITEM_END4  ((NUM_USERS + NUM_ITEMS) * DIM / 4)
#define BR4        ((NUM_BRANDS * DIM) / 4)               // 16,000
#define EMAX       4800000
#define SCAN_CHUNK 1024
#define SCAN_NBLK  ((NTOT + SCAN_CHUNK - 1) / SCAN_CHUNK)  // 148

// Scratch (device globals = sanctioned no-alloc scratch)
__device__ float g_bufA[NDF];
__device__ float g_bufB[NDF];
__device__ float g_acc [NDF];
__device__ int   g_rowptr[NTOT + 1];
__device__ int   g_cursor[NTOT];
__device__ int2  g_ecv[EMAX];            // packed (col, val_bits)
__device__ int   g_bsum[SCAN_NBLK];
__device__ int   g_boff[SCAN_NBLK];

// ---------- packed f32x2 helpers ----------
__device__ __forceinline__ unsigned long long pack2(float lo, float hi) {
    unsigned long long r;
    asm("mov.b64 %0, {%1, %2};" : "=l"(r) : "f"(lo), "f"(hi));
    return r;
}
__device__ __forceinline__ void fma2(unsigned long long& d,
                                     unsigned long long a,
                                     unsigned long long b) {
    asm("fma.rn.f32x2 %0, %1, %2, %0;" : "+l"(d) : "l"(a), "l"(b));
}
__device__ __forceinline__ float2 unpack2(unsigned long long v) {
    float2 r;
    asm("mov.b64 {%0, %1}, %2;" : "=f"(r.x), "=f"(r.y) : "l"(v));
    return r;
}

// ---------------------------------------------------------------------------
// 1) fused_item GEMM: 128x64 block tile, 8x8 thread tile, BK=16, 128 threads,
//    packed f32x2 FMA. Writes item segment of BOTH bufA and acc.
// ---------------------------------------------------------------------------
#define BM 128
#define BN 64
#define BK 16

__global__ __launch_bounds__(128, 4)
void fuse_gemm_kernel(const float* __restrict__ id_emb,
                      const float* __restrict__ content,
                      const float* __restrict__ W,
                      const float* __restrict__ bias,
                      float* __restrict__ outA,
                      float* __restrict__ outAcc) {
    __shared__ float As[BK][BM + 4];   // stride 132 (float4-safe at r%4==0)
    __shared__ float Ws[BK][BN + 4];   // stride 68

    const int tid = threadIdx.x;           // 0..127
    const int tx = tid & 7;                 // 8 col groups of 8
    const int ty = tid >> 3;                // 16 row groups of 8
    const int block_row = blockIdx.x * BM;

    unsigned long long acc2[4][8];
#pragma unroll
    for (int p = 0; p < 4; p++)
#pragma unroll
        for (int j = 0; j < 8; j++) acc2[p][j] = 0ULL;

    for (int k0 = 0; k0 < KDIM; k0 += BK) {
        // Load A tile: 128 rows x 16 k = 512 float4 loads, 4 per thread
#pragma unroll
        for (int i = 0; i < 4; i++) {
            int lin = tid + i * 128;         // 0..511
            int r = lin >> 2;
            int kq = (lin & 3) * 4;
            int gr = block_row + r;
            float4 v = make_float4(0.f, 0.f, 0.f, 0.f);
            if (gr < NUM_ITEMS) {
                int gk = k0 + kq;
                v = (gk < DIM)
                  ? *reinterpret_cast<const float4*>(id_emb + (size_t)gr * DIM + gk)
                  : *reinterpret_cast<const float4*>(content + (size_t)gr * DCONT + (gk - DIM));
            }
            As[kq + 0][r] = v.x;
            As[kq + 1][r] = v.y;
            As[kq + 2][r] = v.z;
            As[kq + 3][r] = v.w;
        }
        // Load W tile: 64 out x 16 k = 256 float4, 2 per thread
#pragma unroll
        for (int i = 0; i < 2; i++) {
            int lin = tid + i * 128;         // 0..255
            int j = lin >> 2;
            int kq = (lin & 3) * 4;
            float4 v = *reinterpret_cast<const float4*>(W + (size_t)j * KDIM + k0 + kq);
            Ws[kq + 0][j] = v.x;
            Ws[kq + 1][j] = v.y;
            Ws[kq + 2][j] = v.z;
            Ws[kq + 3][j] = v.w;
        }
        __syncthreads();

#pragma unroll
        for (int k = 0; k < BK; k++) {
            float4 a01 = *reinterpret_cast<const float4*>(&As[k][ty * 8]);
            float4 a23 = *reinterpret_cast<const float4*>(&As[k][ty * 8 + 4]);
            unsigned long long a2[4];
            a2[0] = pack2(a01.x, a01.y);
            a2[1] = pack2(a01.z, a01.w);
            a2[2] = pack2(a23.x, a23.y);
            a2[3] = pack2(a23.z, a23.w);
            float4 w0 = *reinterpret_cast<const float4*>(&Ws[k][tx * 8]);
            float4 w1 = *reinterpret_cast<const float4*>(&Ws[k][tx * 8 + 4]);
            unsigned long long wb[8];
            wb[0] = pack2(w0.x, w0.x); wb[1] = pack2(w0.y, w0.y);
            wb[2] = pack2(w0.z, w0.z); wb[3] = pack2(w0.w, w0.w);
            wb[4] = pack2(w1.x, w1.x); wb[5] = pack2(w1.y, w1.y);
            wb[6] = pack2(w1.z, w1.z); wb[7] = pack2(w1.w, w1.w);
#pragma unroll
            for (int p = 0; p < 4; p++)
#pragma unroll
                for (int j = 0; j < 8; j++) fma2(acc2[p][j], a2[p], wb[j]);
        }
        __syncthreads();
    }

    // bias for this thread's 8 cols
    float4 b0 = *reinterpret_cast<const float4*>(bias + tx * 8);
    float4 b1 = *reinterpret_cast<const float4*>(bias + tx * 8 + 4);
    float bcol[8] = {b0.x, b0.y, b0.z, b0.w, b1.x, b1.y, b1.z, b1.w};

#pragma unroll
    for (int r = 0; r < 8; r++) {
        int gr = block_row + ty * 8 + r;
        if (gr >= NUM_ITEMS) continue;
        int p = r >> 1;
        float o[8];
#pragma unroll
        for (int j = 0; j < 8; j++) {
            float2 u = unpack2(acc2[p][j]);
            float v = ((r & 1) ? u.y : u.x) + bcol[j];
            o[j] = (v > 0.f) ? v : 0.01f * v;
        }
        float4 s0 = make_float4(o[0], o[1], o[2], o[3]);
        float4 s1 = make_float4(o[4], o[5], o[6], o[7]);
        size_t base = (size_t)gr * DIM + tx * 8;
        *reinterpret_cast<float4*>(outA + base)     = s0;
        *reinterpret_cast<float4*>(outA + base + 4) = s1;
        *reinterpret_cast<float4*>(outAcc + base)     = s0;
        *reinterpret_cast<float4*>(outAcc + base + 4) = s1;
    }
}

// ---------------------------------------------------------------------------
// 2) assemble user+brand segments into bufA and acc (item seg done by GEMM)
// ---------------------------------------------------------------------------
#define INIT4 (UD4 + BR4)
__global__ void init_kernel(float4* __restrict__ A4,
                            float4* __restrict__ acc4,
                            const float4* __restrict__ user4,
                            const float4* __restrict__ brand4) {
    int idx = blockIdx.x * blockDim.x + threadIdx.x;
    if (idx >= INIT4) return;
    float4 v;
    int dst;
    if (idx < UD4) { v = user4[idx]; dst = idx; }
    else           { v = brand4[idx - UD4]; dst = ITEM_END4 + (idx - UD4); }
    A4[dst]   = v;
    acc4[dst] = v;
}

// ---------------------------------------------------------------------------
// CSR build
// ---------------------------------------------------------------------------
__global__ void hist_kernel(const int* __restrict__ rows, int E,
                            int* __restrict__ cnt) {
    int i = blockIdx.x * blockDim.x + threadIdx.x;
    int base = i * 4;
    if (base + 4 <= E) {
        int4 r = *reinterpret_cast<const int4*>(rows + base);
        atomicAdd(&cnt[r.x], 1);
        atomicAdd(&cnt[r.y], 1);
        atomicAdd(&cnt[r.z], 1);
        atomicAdd(&cnt[r.w], 1);
    } else {
        for (int j = base; j < E; j++) atomicAdd(&cnt[rows[j]], 1);
    }
}

__global__ void scan_partial_kernel(const int* __restrict__ cnt,
                                    int* __restrict__ bsum) {
    __shared__ int s[256];
    int b = blockIdx.x, t = threadIdx.x;
    int base = b * SCAN_CHUNK + t * 4;
    int v = 0;
#pragma unroll
    for (int j = 0; j < 4; j++) {
        int idx = base + j;
        if (idx < NTOT) v += cnt[idx];
    }
    s[t] = v;
    __syncthreads();
    for (int off = 128; off > 0; off >>= 1) {
        if (t < off) s[t] += s[t + off];
        __syncthreads();
    }
    if (t == 0) bsum[b] = s[0];
}

__global__ void scan_bsum_kernel(const int* __restrict__ bsum,
                                 int* __restrict__ boff) {
    __shared__ int s[256];
    int t = threadIdx.x;
    int v = (t < SCAN_NBLK) ? bsum[t] : 0;
    s[t] = v;
    __syncthreads();
    for (int off = 1; off < 256; off <<= 1) {
        int tmp = (t >= off) ? s[t - off] : 0;
        __syncthreads();
        s[t] += tmp;
        __syncthreads();
    }
    if (t < SCAN_NBLK) boff[t] = s[t] - v;
}

__global__ void write_rowptr_kernel(const int* __restrict__ cnt,
                                    const int* __restrict__ boff,
                                    int* __restrict__ rp,
                                    int* __restrict__ cur, int E) {
    __shared__ int s[256];
    int b = blockIdx.x, t = threadIdx.x;
    int base = b * SCAN_CHUNK + t * 4;
    int loc[4];
    int v = 0;
#pragma unroll
    for (int j = 0; j < 4; j++) {
        int idx = base + j;
        loc[j] = (idx < NTOT) ? cnt[idx] : 0;
        v += loc[j];
    }
    s[t] = v;
    __syncthreads();
    for (int off = 1; off < 256; off <<= 1) {
        int tmp = (t >= off) ? s[t - off] : 0;
        __syncthreads();
        s[t] += tmp;
        __syncthreads();
    }
    int run = s[t] - v + boff[b];
#pragma unroll
    for (int j = 0; j < 4; j++) {
        int idx = base + j;
        if (idx < NTOT) { rp[idx] = run; cur[idx] = run; }
        run += loc[j];
    }
    if (b == 0 && t == 0) rp[NTOT] = E;
}

__global__ void scatter_kernel(const int* __restrict__ rows,
                               const int* __restrict__ cols,
                               const float* __restrict__ vals, int E,
                               int* __restrict__ cur,
                               long long* __restrict__ ecv) {
    int i = blockIdx.x * blockDim.x + threadIdx.x;
    int base = i * 4;
    if (base + 4 <= E) {
        int4   r = *reinterpret_cast<const int4*>(rows + base);
        int4   c = *reinterpret_cast<const int4*>(cols + base);
        float4 v = *reinterpret_cast<const float4*>(vals + base);
        int p;
        p = atomicAdd(&cur[r.x], 1);
        ecv[p] = ((long long)__float_as_int(v.x) << 32) | (unsigned int)c.x;
        p = atomicAdd(&cur[r.y], 1);
        ecv[p] = ((long long)__float_as_int(v.y) << 32) | (unsigned int)c.y;
        p = atomicAdd(&cur[r.z], 1);
        ecv[p] = ((long long)__float_as_int(v.z) << 32) | (unsigned int)c.z;
        p = atomicAdd(&cur[r.w], 1);
        ecv[p] = ((long long)__float_as_int(v.w) << 32) | (unsigned int)c.w;
    } else {
        for (int j = base; j < E; j++) {
            int p = atomicAdd(&cur[rows[j]], 1);
            ecv[p] = ((long long)__float_as_int(vals[j]) << 32) | (unsigned int)cols[j];
        }
    }
}

// ---------------------------------------------------------------------------
// CSR SpMM: 16 lanes per row, float4 per lane, 4-edge unroll.
// ---------------------------------------------------------------------------
__device__ __forceinline__ float4 fma4(float v, float4 x, float4 a) {
    a.x = fmaf(v, x.x, a.x);
    a.y = fmaf(v, x.y, a.y);
    a.z = fmaf(v, x.z, a.z);
    a.w = fmaf(v, x.w, a.w);
    return a;
}

__global__ void spmm_mid_kernel(const int* __restrict__ rp,
                                const int2* __restrict__ ecv,
                                const float* __restrict__ x,
                                float* __restrict__ y,
                                float* __restrict__ acc) {
    int g = blockIdx.x * blockDim.x + threadIdx.x;
    int row = g >> 4;
    int lane = g & 15;
    if (row >= NTOT) return;
    int s = __ldg(rp + row), e = __ldg(rp + row + 1);
    const float4* X = reinterpret_cast<const float4*>(x);
    float4 a = make_float4(0.f, 0.f, 0.f, 0.f);
    int i = s;
    for (; i + 4 <= e; i += 4) {
        int2 e0 = __ldg(ecv + i),     e1 = __ldg(ecv + i + 1);
        int2 e2 = __ldg(ecv + i + 2), e3 = __ldg(ecv + i + 3);
        float4 x0 = __ldg(X + (size_t)e0.x * 16 + lane);
        float4 x1 = __ldg(X + (size_t)e1.x * 16 + lane);
        float4 x2 = __ldg(X + (size_t)e2.x * 16 + lane);
        float4 x3 = __ldg(X + (size_t)e3.x * 16 + lane);
        a = fma4(__int_as_float(e0.y), x0, a);
        a = fma4(__int_as_float(e1.y), x1, a);
        a = fma4(__int_as_float(e2.y), x2, a);
        a = fma4(__int_as_float(e3.y), x3, a);
    }
    for (; i < e; i++) {
        int2 ee = __ldg(ecv + i);
        float4 xv = __ldg(X + (size_t)ee.x * 16 + lane);
        a = fma4(__int_as_float(ee.y), xv, a);
    }
    size_t o = (size_t)row * 16 + lane;
    reinterpret_cast<float4*>(y)[o] = a;
    float4* A = reinterpret_cast<float4*>(acc);
    float4 av = A[o];
    av.x += a.x; av.y += a.y; av.z += a.z; av.w += a.w;
    A[o] = av;
}

__global__ void spmm_last_kernel(const int* __restrict__ rp,
                                 const int2* __restrict__ ecv,
                                 const float* __restrict__ x,
                                 const float* __restrict__ acc,
                                 float* __restrict__ out) {
    int g = blockIdx.x * blockDim.x + threadIdx.x;
    int row = g >> 4;
    int lane = g & 15;
    if (row >= NTOT) return;
    int s = __ldg(rp + row), e = __ldg(rp + row + 1);
    const float4* X = reinterpret_cast<const float4*>(x);
    float4 a = make_float4(0.f, 0.f, 0.f, 0.f);
    int i = s;
    for (; i + 4 <= e; i += 4) {
        int2 e0 = __ldg(ecv + i),     e1 = __ldg(ecv + i + 1);
        int2 e2 = __ldg(ecv + i + 2), e3 = __ldg(ecv + i + 3);
        float4 x0 = __ldg(X + (size_t)e0.x * 16 + lane);
        float4 x1 = __ldg(X + (size_t)e1.x * 16 + lane);
        float4 x2 = __ldg(X + (size_t)e2.x * 16 + lane);
        float4 x3 = __ldg(X + (size_t)e3.x * 16 + lane);
        a = fma4(__int_as_float(e0.y), x0, a);
        a = fma4(__int_as_float(e1.y), x1, a);
        a = fma4(__int_as_float(e2.y), x2, a);
        a = fma4(__int_as_float(e3.y), x3, a);
    }
    for (; i < e; i++) {
        int2 ee = __ldg(ecv + i);
        float4 xv = __ldg(X + (size_t)ee.x * 16 + lane);
        a = fma4(__int_as_float(ee.y), xv, a);
    }
    size_t o = (size_t)row * 16 + lane;
    float4 av = reinterpret_cast<const float4*>(acc)[o];
    reinterpret_cast<float4*>(out)[o] =
        make_float4((av.x + a.x) * 0.25f, (av.y + a.y) * 0.25f,
                    (av.z + a.z) * 0.25f, (av.w + a.w) * 0.25f);
}

// ---------------------------------------------------------------------------
extern "C" void kernel_launch(void* const* d_in, const int* in_sizes, int n_in,
                              void* d_out, int out_size) {
    const int*   edge_row = (const int*)  d_in[0];
    const int*   edge_col = (const int*)  d_in[1];
    const float* edge_val = (const float*)d_in[2];
    const float* user_emb = (const float*)d_in[3];
    const float* item_id  = (const float*)d_in[4];
    const float* brand    = (const float*)d_in[5];
    const float* content  = (const float*)d_in[6];
    const float* fusion_W = (const float*)d_in[7];
    const float* fusion_b = (const float*)d_in[8];
    const int E = in_sizes[0];

    float *A, *B, *acc;
    int *rp, *cur, *bsum, *boff;
    int2 *ecv;
    cudaGetSymbolAddress((void**)&A,    g_bufA);
    cudaGetSymbolAddress((void**)&B,    g_bufB);
    cudaGetSymbolAddress((void**)&acc,  g_acc);
    cudaGetSymbolAddress((void**)&rp,   g_rowptr);
    cudaGetSymbolAddress((void**)&cur,  g_cursor);
    cudaGetSymbolAddress((void**)&ecv,  g_ecv);
    cudaGetSymbolAddress((void**)&bsum, g_bsum);
    cudaGetSymbolAddress((void**)&boff, g_boff);

    // CSR build
    cudaMemsetAsync(cur, 0, NTOT * sizeof(int));
    int e4blocks = ((E + 3) / 4 + 255) / 256;
    hist_kernel<<<e4blocks, 256>>>(edge_row, E, cur);
    scan_partial_kernel<<<SCAN_NBLK, 256>>>(cur, bsum);
    scan_bsum_kernel<<<1, 256>>>(bsum, boff);
    write_rowptr_kernel<<<SCAN_NBLK, 256>>>(cur, boff, rp, cur, E);
    scatter_kernel<<<e4blocks, 256>>>(edge_row, edge_col, edge_val, E,
                                      cur, (long long*)ecv);

    // Fused item GEMM (writes item segment of A and acc) + user/brand init
    fuse_gemm_kernel<<<(NUM_ITEMS + BM - 1) / BM, 128>>>(
        item_id, content, fusion_W, fusion_b,
        A + (size_t)NUM_USERS * DIM, acc + (size_t)NUM_USERS * DIM);
    init_kernel<<<(INIT4 + 255) / 256, 256>>>(
        (float4*)A, (float4*)acc, (const float4*)user_emb,
        (const float4*)brand);

    // Propagation
    int spmm_blocks = (NTOT * 16 + 255) / 256;
    spmm_mid_kernel<<<spmm_blocks, 256>>>(rp, ecv, A, B, acc);
    spmm_mid_kernel<<<spmm_blocks, 256>>>(rp, ecv, B, A, acc);
    spmm_last_kernel<<<spmm_blocks, 256>>>(rp, ecv, A, acc, (float*)d_out);

    // Echo tensors
    cudaMemcpyAsync((float*)d_out + NDF, user_emb,
                    (size_t)NUM_USERS * DIM * sizeof(float),
                    cudaMemcpyDeviceToDevice);
    cudaMemcpyAsync((float*)d_out + NDF + NUM_USERS * DIM, item_id,
                    (size_t)NUM_ITEMS * DIM * sizeof(float),
                    cudaMemcpyDeviceToDevice);
}

// round 4
// speedup vs baseline: 2.2614x; 1.0260x over previous
#include <cuda_runtime.h>
#include <cuda_bf16.h>
#include <cstdint>

#define NUM_USERS  100000
#define NUM_ITEMS  50000
#define NUM_BRANDS 1000
#define NTOT       (NUM_USERS + NUM_ITEMS + NUM_BRANDS)   // 151000
#define DIM        64
#define DCONT      384
#define KDIM       (DIM + DCONT)                          // 448
#define NDF        (NTOT * DIM)
#define ND4        (NDF / 4)
#define UD4        (NUM_USERS * DIM / 4)                  // 1,600,000
#define ID4        ((NUM_ITEMS * DIM) / 4)                // 800,000
#define ITEM_END4  ((NUM_USERS + NUM_ITEMS) * DIM / 4)
#define BR4        ((NUM_BRANDS * DIM) / 4)               // 16,000
#define INIT4      (UD4 + BR4)
#define ECHO4      (UD4 + ID4)                            // 2,400,000
#define EMAX       4800000
#define SCAN_CHUNK 1024
#define SCAN_NBLK  ((NTOT + SCAN_CHUNK - 1) / SCAN_CHUNK)  // 148

#define BM 128
#define BN 64
#define BK 16
#define GEMM_BLOCKS ((NUM_ITEMS + BM - 1) / BM)            // 391

// Scratch (device globals = sanctioned no-alloc scratch)
__device__ float g_bufA[NDF];
__device__ float g_bufB[NDF];
__device__ float g_acc [NDF];
__device__ int   g_rowptr[NTOT + 1];
__device__ int   g_cursor[NTOT];
__device__ int2  g_ecv[EMAX];            // packed (col, val_bits)
__device__ int   g_bsum[SCAN_NBLK];
__device__ int   g_boff[SCAN_NBLK];

// ---------- packed f32x2 helpers ----------
__device__ __forceinline__ unsigned long long pack2(float lo, float hi) {
    unsigned long long r;
    asm("mov.b64 %0, {%1, %2};" : "=l"(r) : "f"(lo), "f"(hi));
    return r;
}
__device__ __forceinline__ void fma2(unsigned long long& d,
                                     unsigned long long a,
                                     unsigned long long b) {
    asm("fma.rn.f32x2 %0, %1, %2, %0;" : "+l"(d) : "l"(a), "l"(b));
}
__device__ __forceinline__ float2 unpack2(unsigned long long v) {
    float2 r;
    asm("mov.b64 {%0, %1}, %2;" : "=f"(r.x), "=f"(r.y) : "l"(v));
    return r;
}

// ---------------------------------------------------------------------------
// GEMM device path: 128x64 block tile, 256 threads, 4x8 thread tile, f32x2.
// Writes leaky_relu result into item segment of BOTH bufA and acc.
// ---------------------------------------------------------------------------
__device__ void gemm_path(int gblk, int tid,
                          const float* __restrict__ id_emb,
                          const float* __restrict__ content,
                          const float* __restrict__ W,
                          const float* __restrict__ bias,
                          float* __restrict__ outA,
                          float* __restrict__ outAcc,
                          float* smem_raw) {
    float (*As)[BM + 4] = reinterpret_cast<float (*)[BM + 4]>(smem_raw);
    float (*Ws)[BN + 4] = reinterpret_cast<float (*)[BN + 4]>(smem_raw + BK * (BM + 4));

    const int tx = tid & 7;     // 8 col groups of 8
    const int ty = tid >> 3;    // 32 row groups of 4
    const int block_row = gblk * BM;

    unsigned long long acc2[2][8];
#pragma unroll
    for (int p = 0; p < 2; p++)
#pragma unroll
        for (int j = 0; j < 8; j++) acc2[p][j] = 0ULL;

    for (int k0 = 0; k0 < KDIM; k0 += BK) {
        // A tile: 128 rows x 16 k = 512 float4, 2 per thread
#pragma unroll
        for (int i = 0; i < 2; i++) {
            int lin = tid + i * 256;
            int r = lin >> 2;
            int kq = (lin & 3) * 4;
            int gr = block_row + r;
            float4 v = make_float4(0.f, 0.f, 0.f, 0.f);
            if (gr < NUM_ITEMS) {
                int gk = k0 + kq;
                v = (gk < DIM)
                  ? *reinterpret_cast<const float4*>(id_emb + (size_t)gr * DIM + gk)
                  : *reinterpret_cast<const float4*>(content + (size_t)gr * DCONT + (gk - DIM));
            }
            As[kq + 0][r] = v.x;
            As[kq + 1][r] = v.y;
            As[kq + 2][r] = v.z;
            As[kq + 3][r] = v.w;
        }
        // W tile: 64 out x 16 k = 256 float4, 1 per thread
        {
            int j = tid >> 2;
            int kq = (tid & 3) * 4;
            float4 v = *reinterpret_cast<const float4*>(W + (size_t)j * KDIM + k0 + kq);
            Ws[kq + 0][j] = v.x;
            Ws[kq + 1][j] = v.y;
            Ws[kq + 2][j] = v.z;
            Ws[kq + 3][j] = v.w;
        }
        __syncthreads();

#pragma unroll
        for (int k = 0; k < BK; k++) {
            float4 a4 = *reinterpret_cast<const float4*>(&As[k][ty * 4]);
            unsigned long long a2[2];
            a2[0] = pack2(a4.x, a4.y);
            a2[1] = pack2(a4.z, a4.w);
            float4 w0 = *reinterpret_cast<const float4*>(&Ws[k][tx * 8]);
            float4 w1 = *reinterpret_cast<const float4*>(&Ws[k][tx * 8 + 4]);
            unsigned long long wb[8];
            wb[0] = pack2(w0.x, w0.x); wb[1] = pack2(w0.y, w0.y);
            wb[2] = pack2(w0.z, w0.z); wb[3] = pack2(w0.w, w0.w);
            wb[4] = pack2(w1.x, w1.x); wb[5] = pack2(w1.y, w1.y);
            wb[6] = pack2(w1.z, w1.z); wb[7] = pack2(w1.w, w1.w);
#pragma unroll
            for (int p = 0; p < 2; p++)
#pragma unroll
                for (int j = 0; j < 8; j++) fma2(acc2[p][j], a2[p], wb[j]);
        }
        __syncthreads();
    }

    float4 b0 = *reinterpret_cast<const float4*>(bias + tx * 8);
    float4 b1 = *reinterpret_cast<const float4*>(bias + tx * 8 + 4);
    float bcol[8] = {b0.x, b0.y, b0.z, b0.w, b1.x, b1.y, b1.z, b1.w};

#pragma unroll
    for (int r = 0; r < 4; r++) {
        int gr = block_row + ty * 4 + r;
        if (gr >= NUM_ITEMS) continue;
        int p = r >> 1;
        float o[8];
#pragma unroll
        for (int j = 0; j < 8; j++) {
            float2 u = unpack2(acc2[p][j]);
            float v = ((r & 1) ? u.y : u.x) + bcol[j];
            o[j] = (v > 0.f) ? v : 0.01f * v;
        }
        float4 s0 = make_float4(o[0], o[1], o[2], o[3]);
        float4 s1 = make_float4(o[4], o[5], o[6], o[7]);
        size_t base = (size_t)gr * DIM + tx * 8;
        *reinterpret_cast<float4*>(outA + base)       = s0;
        *reinterpret_cast<float4*>(outA + base + 4)   = s1;
        *reinterpret_cast<float4*>(outAcc + base)     = s0;
        *reinterpret_cast<float4*>(outAcc + base + 4) = s1;
    }
}

// ---------------------------------------------------------------------------
// K1 mega-kernel: [0,G) gemm | [G,G+H) hist | [G+H, ...) user/brand init
// ---------------------------------------------------------------------------
__global__ __launch_bounds__(256)
void mega1_kernel(const float* __restrict__ id_emb,
                  const float* __restrict__ content,
                  const float* __restrict__ W,
                  const float* __restrict__ bias,
                  const float* __restrict__ user_emb,
                  const float* __restrict__ brand,
                  const int*   __restrict__ rows, int E, int histBlocks,
                  int* __restrict__ cnt,
                  float* __restrict__ A,
                  float* __restrict__ acc) {
    __shared__ float smem_raw[BK * (BM + 4) + BK * (BN + 4)];
    int b = blockIdx.x;
    int tid = threadIdx.x;

    if (b < GEMM_BLOCKS) {
        gemm_path(b, tid, id_emb, content, W, bias,
                  A + (size_t)NUM_USERS * DIM, acc + (size_t)NUM_USERS * DIM,
                  smem_raw);
        return;
    }
    b -= GEMM_BLOCKS;
    if (b < histBlocks) {
        int base = (b * 256 + tid) * 4;
        if (base + 4 <= E) {
            int4 r = *reinterpret_cast<const int4*>(rows + base);
            atomicAdd(&cnt[r.x], 1);
            atomicAdd(&cnt[r.y], 1);
            atomicAdd(&cnt[r.z], 1);
            atomicAdd(&cnt[r.w], 1);
        } else {
            for (int j = base; j < E; j++) atomicAdd(&cnt[rows[j]], 1);
        }
        return;
    }
    b -= histBlocks;
    int idx = b * 256 + tid;
    if (idx >= INIT4) return;
    const float4* user4  = reinterpret_cast<const float4*>(user_emb);
    const float4* brand4 = reinterpret_cast<const float4*>(brand);
    float4* A4   = reinterpret_cast<float4*>(A);
    float4* acc4 = reinterpret_cast<float4*>(acc);
    float4 v;
    int dst;
    if (idx < UD4) { v = user4[idx]; dst = idx; }
    else           { v = brand4[idx - UD4]; dst = ITEM_END4 + (idx - UD4); }
    A4[dst]   = v;
    acc4[dst] = v;
}

// ---------------------------------------------------------------------------
// CSR build helpers
// ---------------------------------------------------------------------------
__global__ void scan_partial_kernel(const int* __restrict__ cnt,
                                    int* __restrict__ bsum) {
    __shared__ int s[256];
    int b = blockIdx.x, t = threadIdx.x;
    int base = b * SCAN_CHUNK + t * 4;
    int v = 0;
#pragma unroll
    for (int j = 0; j < 4; j++) {
        int idx = base + j;
        if (idx < NTOT) v += cnt[idx];
    }
    s[t] = v;
    __syncthreads();
    for (int off = 128; off > 0; off >>= 1) {
        if (t < off) s[t] += s[t + off];
        __syncthreads();
    }
    if (t == 0) bsum[b] = s[0];
}

__global__ void scan_bsum_kernel(const int* __restrict__ bsum,
                                 int* __restrict__ boff) {
    __shared__ int s[256];
    int t = threadIdx.x;
    int v = (t < SCAN_NBLK) ? bsum[t] : 0;
    s[t] = v;
    __syncthreads();
    for (int off = 1; off < 256; off <<= 1) {
        int tmp = (t >= off) ? s[t - off] : 0;
        __syncthreads();
        s[t] += tmp;
        __syncthreads();
    }
    if (t < SCAN_NBLK) boff[t] = s[t] - v;
}

__global__ void write_rowptr_kernel(const int* __restrict__ cnt,
                                    const int* __restrict__ boff,
                                    int* __restrict__ rp,
                                    int* __restrict__ cur, int E) {
    __shared__ int s[256];
    int b = blockIdx.x, t = threadIdx.x;
    int base = b * SCAN_CHUNK + t * 4;
    int loc[4];
    int v = 0;
#pragma unroll
    for (int j = 0; j < 4; j++) {
        int idx = base + j;
        loc[j] = (idx < NTOT) ? cnt[idx] : 0;
        v += loc[j];
    }
    s[t] = v;
    __syncthreads();
    for (int off = 1; off < 256; off <<= 1) {
        int tmp = (t >= off) ? s[t - off] : 0;
        __syncthreads();
        s[t] += tmp;
        __syncthreads();
    }
    int run = s[t] - v + boff[b];
#pragma unroll
    for (int j = 0; j < 4; j++) {
        int idx = base + j;
        if (idx < NTOT) { rp[idx] = run; cur[idx] = run; }
        run += loc[j];
    }
    if (b == 0 && t == 0) rp[NTOT] = E;
}

__global__ void scatter_kernel(const int* __restrict__ rows,
                               const int* __restrict__ cols,
                               const float* __restrict__ vals, int E,
                               int* __restrict__ cur,
                               long long* __restrict__ ecv) {
    int i = blockIdx.x * blockDim.x + threadIdx.x;
    int base = i * 4;
    if (base + 4 <= E) {
        int4   r = *reinterpret_cast<const int4*>(rows + base);
        int4   c = *reinterpret_cast<const int4*>(cols + base);
        float4 v = *reinterpret_cast<const float4*>(vals + base);
        int p;
        p = atomicAdd(&cur[r.x], 1);
        ecv[p] = ((long long)__float_as_int(v.x) << 32) | (unsigned int)c.x;
        p = atomicAdd(&cur[r.y], 1);
        ecv[p] = ((long long)__float_as_int(v.y) << 32) | (unsigned int)c.y;
        p = atomicAdd(&cur[r.z], 1);
        ecv[p] = ((long long)__float_as_int(v.z) << 32) | (unsigned int)c.z;
        p = atomicAdd(&cur[r.w], 1);
        ecv[p] = ((long long)__float_as_int(v.w) << 32) | (unsigned int)c.w;
    } else {
        for (int j = base; j < E; j++) {
            int p = atomicAdd(&cur[rows[j]], 1);
            ecv[p] = ((long long)__float_as_int(vals[j]) << 32) | (unsigned int)cols[j];
        }
    }
}

// ---------------------------------------------------------------------------
// CSR SpMM: 16 lanes per row, float4 per lane, 4-edge unroll.
// ---------------------------------------------------------------------------
__device__ __forceinline__ float4 fma4(float v, float4 x, float4 a) {
    a.x = fmaf(v, x.x, a.x);
    a.y = fmaf(v, x.y, a.y);
    a.z = fmaf(v, x.z, a.z);
    a.w = fmaf(v, x.w, a.w);
    return a;
}

__device__ __forceinline__ float4 spmm_row(const int* __restrict__ rp,
                                           const int2* __restrict__ ecv,
                                           const float4* __restrict__ X,
                                           int row, int lane) {
    int s = __ldg(rp + row), e = __ldg(rp + row + 1);
    float4 a = make_float4(0.f, 0.f, 0.f, 0.f);
    int i = s;
    for (; i + 4 <= e; i += 4) {
        int2 e0 = __ldg(ecv + i),     e1 = __ldg(ecv + i + 1);
        int2 e2 = __ldg(ecv + i + 2), e3 = __ldg(ecv + i + 3);
        float4 x0 = __ldg(X + (size_t)e0.x * 16 + lane);
        float4 x1 = __ldg(X + (size_t)e1.x * 16 + lane);
        float4 x2 = __ldg(X + (size_t)e2.x * 16 + lane);
        float4 x3 = __ldg(X + (size_t)e3.x * 16 + lane);
        a = fma4(__int_as_float(e0.y), x0, a);
        a = fma4(__int_as_float(e1.y), x1, a);
        a = fma4(__int_as_float(e2.y), x2, a);
        a = fma4(__int_as_float(e3.y), x3, a);
    }
    for (; i < e; i++) {
        int2 ee = __ldg(ecv + i);
        float4 xv = __ldg(X + (size_t)ee.x * 16 + lane);
        a = fma4(__int_as_float(ee.y), xv, a);
    }
    return a;
}

#define SPMM_BLOCKS ((NTOT * 16 + 255) / 256)
#define ECHO_BLOCKS ((ECHO4 + 255) / 256)

// First SpMM layer + echo copies folded in as extra blocks.
__global__ void spmm1_mega_kernel(const int* __restrict__ rp,
                                  const int2* __restrict__ ecv,
                                  const float* __restrict__ x,
                                  float* __restrict__ y,
                                  float* __restrict__ acc,
                                  const float* __restrict__ user_emb,
                                  const float* __restrict__ item_id,
                                  float* __restrict__ out) {
    int b = blockIdx.x;
    int tid = threadIdx.x;
    if (b < SPMM_BLOCKS) {
        int g = b * 256 + tid;
        int row = g >> 4;
        int lane = g & 15;
        if (row >= NTOT) return;
        float4 a = spmm_row(rp, ecv, reinterpret_cast<const float4*>(x), row, lane);
        size_t o = (size_t)row * 16 + lane;
        reinterpret_cast<float4*>(y)[o] = a;
        float4* A = reinterpret_cast<float4*>(acc);
        float4 av = A[o];
        av.x += a.x; av.y += a.y; av.z += a.z; av.w += a.w;
        A[o] = av;
        return;
    }
    b -= SPMM_BLOCKS;
    int idx = b * 256 + tid;
    if (idx >= ECHO4) return;
    float4 v = (idx < UD4)
             ? reinterpret_cast<const float4*>(user_emb)[idx]
             : reinterpret_cast<const float4*>(item_id)[idx - UD4];
    reinterpret_cast<float4*>(out)[ND4 + idx] = v;
}

__global__ void spmm_mid_kernel(const int* __restrict__ rp,
                                const int2* __restrict__ ecv,
                                const float* __restrict__ x,
                                float* __restrict__ y,
                                float* __restrict__ acc) {
    int g = blockIdx.x * blockDim.x + threadIdx.x;
    int row = g >> 4;
    int lane = g & 15;
    if (row >= NTOT) return;
    float4 a = spmm_row(rp, ecv, reinterpret_cast<const float4*>(x), row, lane);
    size_t o = (size_t)row * 16 + lane;
    reinterpret_cast<float4*>(y)[o] = a;
    float4* A = reinterpret_cast<float4*>(acc);
    float4 av = A[o];
    av.x += a.x; av.y += a.y; av.z += a.z; av.w += a.w;
    A[o] = av;
}

__global__ void spmm_last_kernel(const int* __restrict__ rp,
                                 const int2* __restrict__ ecv,
                                 const float* __restrict__ x,
                                 const float* __restrict__ acc,
                                 float* __restrict__ out) {
    int g = blockIdx.x * blockDim.x + threadIdx.x;
    int row = g >> 4;
    int lane = g & 15;
    if (row >= NTOT) return;
    float4 a = spmm_row(rp, ecv, reinterpret_cast<const float4*>(x), row, lane);
    size_t o = (size_t)row * 16 + lane;
    float4 av = reinterpret_cast<const float4*>(acc)[o];
    reinterpret_cast<float4*>(out)[o] =
        make_float4((av.x + a.x) * 0.25f, (av.y + a.y) * 0.25f,
                    (av.z + a.z) * 0.25f, (av.w + a.w) * 0.25f);
}

// ---------------------------------------------------------------------------
extern "C" void kernel_launch(void* const* d_in, const int* in_sizes, int n_in,
                              void* d_out, int out_size) {
    const int*   edge_row = (const int*)  d_in[0];
    const int*   edge_col = (const int*)  d_in[1];
    const float* edge_val = (const float*)d_in[2];
    const float* user_emb = (const float*)d_in[3];
    const float* item_id  = (const float*)d_in[4];
    const float* brand    = (const float*)d_in[5];
    const float* content  = (const float*)d_in[6];
    const float* fusion_W = (const float*)d_in[7];
    const float* fusion_b = (const float*)d_in[8];
    const int E = in_sizes[0];

    float *A, *B, *acc;
    int *rp, *cur, *bsum, *boff;
    int2 *ecv;
    cudaGetSymbolAddress((void**)&A,    g_bufA);
    cudaGetSymbolAddress((void**)&B,    g_bufB);
    cudaGetSymbolAddress((void**)&acc,  g_acc);
    cudaGetSymbolAddress((void**)&rp,   g_rowptr);
    cudaGetSymbolAddress((void**)&cur,  g_cursor);
    cudaGetSymbolAddress((void**)&ecv,  g_ecv);
    cudaGetSymbolAddress((void**)&bsum, g_bsum);
    cudaGetSymbolAddress((void**)&boff, g_boff);

    cudaMemsetAsync(cur, 0, NTOT * sizeof(int));

    // K1: GEMM + hist + user/brand init, one wave-overlapped launch
    int histBlocks = ((E + 3) / 4 + 255) / 256;
    int initBlocks = (INIT4 + 255) / 256;
    mega1_kernel<<<GEMM_BLOCKS + histBlocks + initBlocks, 256>>>(
        item_id, content, fusion_W, fusion_b, user_emb, brand,
        edge_row, E, histBlocks, cur, A, acc);

    // CSR scan + scatter
    scan_partial_kernel<<<SCAN_NBLK, 256>>>(cur, bsum);
    scan_bsum_kernel<<<1, 256>>>(bsum, boff);
    write_rowptr_kernel<<<SCAN_NBLK, 256>>>(cur, boff, rp, cur, E);
    scatter_kernel<<<((E + 3) / 4 + 255) / 256, 256>>>(
        edge_row, edge_col, edge_val, E, cur, (long long*)ecv);

    // Propagation (layer 1 carries the echo copies)
    spmm1_mega_kernel<<<SPMM_BLOCKS + ECHO_BLOCKS, 256>>>(
        rp, ecv, A, B, acc, user_emb, item_id, (float*)d_out);
    spmm_mid_kernel<<<SPMM_BLOCKS, 256>>>(rp, ecv, B, A, acc);
    spmm_last_kernel<<<SPMM_BLOCKS, 256>>>(rp, ecv, A, acc, (float*)d_out);
}

// round 5
// speedup vs baseline: 2.3808x; 1.0528x over previous
#include <cuda_runtime.h>
#include <cuda_bf16.h>
#include <cstdint>

#define NUM_USERS  100000
#define NUM_ITEMS  50000
#define NUM_BRANDS 1000
#define NTOT       (NUM_USERS + NUM_ITEMS + NUM_BRANDS)   // 151000
#define DIM        64
#define DCONT      384
#define KDIM       (DIM + DCONT)                          // 448
#define NDF        (NTOT * DIM)
#define ND4        (NDF / 4)
#define UD4        (NUM_USERS * DIM / 4)                  // 1,600,000
#define ID4        ((NUM_ITEMS * DIM) / 4)                // 800,000
#define ITEM_END4  ((NUM_USERS + NUM_ITEMS) * DIM / 4)
#define BR4        ((NUM_BRANDS * DIM) / 4)               // 16,000
#define INIT4      (UD4 + BR4)
#define ECHO4      (UD4 + ID4)                            // 2,400,000
#define EMAX       4800000
#define SCAN_CHUNK 1024
#define SCAN_NBLK  ((NTOT + SCAN_CHUNK - 1) / SCAN_CHUNK)  // 148

#define BM 128
#define BN 64
#define BK 16
#define GEMM_BLOCKS ((NUM_ITEMS + BM - 1) / BM)            // 391

// Scratch (device globals = sanctioned no-alloc scratch)
__device__ float g_bufA[NDF];   // ego
__device__ float g_bufB[NDF];   // y1
__device__ float g_bufC[NDF];   // y2
__device__ int   g_rowptr[NTOT + 1];
__device__ int   g_cursor[NTOT];
__device__ int2  g_ecv[EMAX];            // packed (col, val_bits)
__device__ int   g_bsum[SCAN_NBLK];

// ---------- packed f32x2 helpers ----------
__device__ __forceinline__ unsigned long long pack2(float lo, float hi) {
    unsigned long long r;
    asm("mov.b64 %0, {%1, %2};" : "=l"(r) : "f"(lo), "f"(hi));
    return r;
}
__device__ __forceinline__ void fma2(unsigned long long& d,
                                     unsigned long long a,
                                     unsigned long long b) {
    asm("fma.rn.f32x2 %0, %1, %2, %0;" : "+l"(d) : "l"(a), "l"(b));
}
__device__ __forceinline__ float2 unpack2(unsigned long long v) {
    float2 r;
    asm("mov.b64 {%0, %1}, %2;" : "=f"(r.x), "=f"(r.y) : "l"(v));
    return r;
}

// ---------------------------------------------------------------------------
// GEMM device path: 128x64 block tile, 256 threads, 4x8 thread tile, f32x2.
// Writes leaky_relu result into item segment of bufA (ego).
// ---------------------------------------------------------------------------
__device__ void gemm_path(int gblk, int tid,
                          const float* __restrict__ id_emb,
                          const float* __restrict__ content,
                          const float* __restrict__ W,
                          const float* __restrict__ bias,
                          float* __restrict__ outA,
                          float* smem_raw) {
    float (*As)[BM + 4] = reinterpret_cast<float (*)[BM + 4]>(smem_raw);
    float (*Ws)[BN + 4] = reinterpret_cast<float (*)[BN + 4]>(smem_raw + BK * (BM + 4));

    const int tx = tid & 7;     // 8 col groups of 8
    const int ty = tid >> 3;    // 32 row groups of 4
    const int block_row = gblk * BM;

    unsigned long long acc2[2][8];
#pragma unroll
    for (int p = 0; p < 2; p++)
#pragma unroll
        for (int j = 0; j < 8; j++) acc2[p][j] = 0ULL;

    for (int k0 = 0; k0 < KDIM; k0 += BK) {
#pragma unroll
        for (int i = 0; i < 2; i++) {
            int lin = tid + i * 256;
            int r = lin >> 2;
            int kq = (lin & 3) * 4;
            int gr = block_row + r;
            float4 v = make_float4(0.f, 0.f, 0.f, 0.f);
            if (gr < NUM_ITEMS) {
                int gk = k0 + kq;
                v = (gk < DIM)
                  ? *reinterpret_cast<const float4*>(id_emb + (size_t)gr * DIM + gk)
                  : *reinterpret_cast<const float4*>(content + (size_t)gr * DCONT + (gk - DIM));
            }
            As[kq + 0][r] = v.x;
            As[kq + 1][r] = v.y;
            As[kq + 2][r] = v.z;
            As[kq + 3][r] = v.w;
        }
        {
            int j = tid >> 2;
            int kq = (tid & 3) * 4;
            float4 v = *reinterpret_cast<const float4*>(W + (size_t)j * KDIM + k0 + kq);
            Ws[kq + 0][j] = v.x;
            Ws[kq + 1][j] = v.y;
            Ws[kq + 2][j] = v.z;
            Ws[kq + 3][j] = v.w;
        }
        __syncthreads();

#pragma unroll
        for (int k = 0; k < BK; k++) {
            float4 a4 = *reinterpret_cast<const float4*>(&As[k][ty * 4]);
            unsigned long long a2[2];
            a2[0] = pack2(a4.x, a4.y);
            a2[1] = pack2(a4.z, a4.w);
            float4 w0 = *reinterpret_cast<const float4*>(&Ws[k][tx * 8]);
            float4 w1 = *reinterpret_cast<const float4*>(&Ws[k][tx * 8 + 4]);
            unsigned long long wb[8];
            wb[0] = pack2(w0.x, w0.x); wb[1] = pack2(w0.y, w0.y);
            wb[2] = pack2(w0.z, w0.z); wb[3] = pack2(w0.w, w0.w);
            wb[4] = pack2(w1.x, w1.x); wb[5] = pack2(w1.y, w1.y);
            wb[6] = pack2(w1.z, w1.z); wb[7] = pack2(w1.w, w1.w);
#pragma unroll
            for (int p = 0; p < 2; p++)
#pragma unroll
                for (int j = 0; j < 8; j++) fma2(acc2[p][j], a2[p], wb[j]);
        }
        __syncthreads();
    }

    float4 b0 = *reinterpret_cast<const float4*>(bias + tx * 8);
    float4 b1 = *reinterpret_cast<const float4*>(bias + tx * 8 + 4);
    float bcol[8] = {b0.x, b0.y, b0.z, b0.w, b1.x, b1.y, b1.z, b1.w};

#pragma unroll
    for (int r = 0; r < 4; r++) {
        int gr = block_row + ty * 4 + r;
        if (gr >= NUM_ITEMS) continue;
        int p = r >> 1;
        float o[8];
#pragma unroll
        for (int j = 0; j < 8; j++) {
            float2 u = unpack2(acc2[p][j]);
            float v = ((r & 1) ? u.y : u.x) + bcol[j];
            o[j] = (v > 0.f) ? v : 0.01f * v;
        }
        size_t base = (size_t)gr * DIM + tx * 8;
        *reinterpret_cast<float4*>(outA + base)     = make_float4(o[0], o[1], o[2], o[3]);
        *reinterpret_cast<float4*>(outA + base + 4) = make_float4(o[4], o[5], o[6], o[7]);
    }
}

// ---------------------------------------------------------------------------
// K1 mega-kernel: [0,G) gemm | [G,G+H) hist | [G+H, ...) user/brand init
// ---------------------------------------------------------------------------
__global__ __launch_bounds__(256)
void mega1_kernel(const float* __restrict__ id_emb,
                  const float* __restrict__ content,
                  const float* __restrict__ W,
                  const float* __restrict__ bias,
                  const float* __restrict__ user_emb,
                  const float* __restrict__ brand,
                  const int*   __restrict__ rows, int E, int histBlocks,
                  int* __restrict__ cnt,
                  float* __restrict__ A) {
    __shared__ float smem_raw[BK * (BM + 4) + BK * (BN + 4)];
    int b = blockIdx.x;
    int tid = threadIdx.x;

    if (b < GEMM_BLOCKS) {
        gemm_path(b, tid, id_emb, content, W, bias,
                  A + (size_t)NUM_USERS * DIM, smem_raw);
        return;
    }
    b -= GEMM_BLOCKS;
    if (b < histBlocks) {
        int base = (b * 256 + tid) * 4;
        if (base + 4 <= E) {
            int4 r = *reinterpret_cast<const int4*>(rows + base);
            atomicAdd(&cnt[r.x], 1);
            atomicAdd(&cnt[r.y], 1);
            atomicAdd(&cnt[r.z], 1);
            atomicAdd(&cnt[r.w], 1);
        } else {
            for (int j = base; j < E; j++) atomicAdd(&cnt[rows[j]], 1);
        }
        return;
    }
    b -= histBlocks;
    int idx = b * 256 + tid;
    if (idx >= INIT4) return;
    const float4* user4  = reinterpret_cast<const float4*>(user_emb);
    const float4* brand4 = reinterpret_cast<const float4*>(brand);
    float4* A4 = reinterpret_cast<float4*>(A);
    if (idx < UD4) A4[idx] = user4[idx];
    else           A4[ITEM_END4 + (idx - UD4)] = brand4[idx - UD4];
}

// ---------------------------------------------------------------------------
// CSR build: partial sums, then fused (bsum-scan + rowptr write)
// ---------------------------------------------------------------------------
__global__ void scan_partial_kernel(const int* __restrict__ cnt,
                                    int* __restrict__ bsum) {
    __shared__ int s[256];
    int b = blockIdx.x, t = threadIdx.x;
    int base = b * SCAN_CHUNK + t * 4;
    int v = 0;
#pragma unroll
    for (int j = 0; j < 4; j++) {
        int idx = base + j;
        if (idx < NTOT) v += cnt[idx];
    }
    s[t] = v;
    __syncthreads();
    for (int off = 128; off > 0; off >>= 1) {
        if (t < off) s[t] += s[t + off];
        __syncthreads();
    }
    if (t == 0) bsum[b] = s[0];
}

__global__ void write_rowptr_kernel(const int* __restrict__ cnt,
                                    const int* __restrict__ bsum,
                                    int* __restrict__ rp,
                                    int* __restrict__ cur, int E) {
    __shared__ int sb[256];
    __shared__ int s[256];
    int b = blockIdx.x, t = threadIdx.x;

    // Redundant per-block scan of the 148 block sums -> boff for this block
    int bv = (t < SCAN_NBLK) ? bsum[t] : 0;
    sb[t] = bv;
    __syncthreads();
    for (int off = 1; off < 256; off <<= 1) {
        int tmp = (t >= off) ? sb[t - off] : 0;
        __syncthreads();
        sb[t] += tmp;
        __syncthreads();
    }
    int boff_b = sb[b] - bsum[b];   // exclusive prefix of this block
    __syncthreads();

    int base = b * SCAN_CHUNK + t * 4;
    int loc[4];
    int v = 0;
#pragma unroll
    for (int j = 0; j < 4; j++) {
        int idx = base + j;
        loc[j] = (idx < NTOT) ? cnt[idx] : 0;
        v += loc[j];
    }
    s[t] = v;
    __syncthreads();
    for (int off = 1; off < 256; off <<= 1) {
        int tmp = (t >= off) ? s[t - off] : 0;
        __syncthreads();
        s[t] += tmp;
        __syncthreads();
    }
    int run = s[t] - v + boff_b;
#pragma unroll
    for (int j = 0; j < 4; j++) {
        int idx = base + j;
        if (idx < NTOT) { rp[idx] = run; cur[idx] = run; }
        run += loc[j];
    }
    if (b == 0 && t == 0) rp[NTOT] = E;
}

__global__ void scatter_kernel(const int* __restrict__ rows,
                               const int* __restrict__ cols,
                               const float* __restrict__ vals, int E,
                               int* __restrict__ cur,
                               long long* __restrict__ ecv) {
    int i = blockIdx.x * blockDim.x + threadIdx.x;
    int base = i * 4;
    if (base + 4 <= E) {
        int4   r = *reinterpret_cast<const int4*>(rows + base);
        int4   c = *reinterpret_cast<const int4*>(cols + base);
        float4 v = *reinterpret_cast<const float4*>(vals + base);
        int p;
        p = atomicAdd(&cur[r.x], 1);
        ecv[p] = ((long long)__float_as_int(v.x) << 32) | (unsigned int)c.x;
        p = atomicAdd(&cur[r.y], 1);
        ecv[p] = ((long long)__float_as_int(v.y) << 32) | (unsigned int)c.y;
        p = atomicAdd(&cur[r.z], 1);
        ecv[p] = ((long long)__float_as_int(v.z) << 32) | (unsigned int)c.z;
        p = atomicAdd(&cur[r.w], 1);
        ecv[p] = ((long long)__float_as_int(v.w) << 32) | (unsigned int)c.w;
    } else {
        for (int j = base; j < E; j++) {
            int p = atomicAdd(&cur[rows[j]], 1);
            ecv[p] = ((long long)__float_as_int(vals[j]) << 32) | (unsigned int)cols[j];
        }
    }
}

// ---------------------------------------------------------------------------
// CSR SpMM: 16 lanes per row, float4 per lane, 4-edge unroll.
// ---------------------------------------------------------------------------
__device__ __forceinline__ float4 fma4(float v, float4 x, float4 a) {
    a.x = fmaf(v, x.x, a.x);
    a.y = fmaf(v, x.y, a.y);
    a.z = fmaf(v, x.z, a.z);
    a.w = fmaf(v, x.w, a.w);
    return a;
}

__device__ __forceinline__ float4 spmm_row(const int* __restrict__ rp,
                                           const int2* __restrict__ ecv,
                                           const float4* __restrict__ X,
                                           int row, int lane) {
    int s = __ldg(rp + row), e = __ldg(rp + row + 1);
    float4 a = make_float4(0.f, 0.f, 0.f, 0.f);
    int i = s;
    for (; i + 4 <= e; i += 4) {
        int2 e0 = __ldg(ecv + i),     e1 = __ldg(ecv + i + 1);
        int2 e2 = __ldg(ecv + i + 2), e3 = __ldg(ecv + i + 3);
        float4 x0 = __ldg(X + (size_t)e0.x * 16 + lane);
        float4 x1 = __ldg(X + (size_t)e1.x * 16 + lane);
        float4 x2 = __ldg(X + (size_t)e2.x * 16 + lane);
        float4 x3 = __ldg(X + (size_t)e3.x * 16 + lane);
        a = fma4(__int_as_float(e0.y), x0, a);
        a = fma4(__int_as_float(e1.y), x1, a);
        a = fma4(__int_as_float(e2.y), x2, a);
        a = fma4(__int_as_float(e3.y), x3, a);
    }
    for (; i < e; i++) {
        int2 ee = __ldg(ecv + i);
        float4 xv = __ldg(X + (size_t)ee.x * 16 + lane);
        a = fma4(__int_as_float(ee.y), xv, a);
    }
    return a;
}

#define SPMM_BLOCKS ((NTOT * 16 + 255) / 256)
#define ECHO_BLOCKS ((ECHO4 + 255) / 256)

// Layer 1: y1 = spmm(A); echo copies folded in as extra blocks.
__global__ void spmm1_mega_kernel(const int* __restrict__ rp,
                                  const int2* __restrict__ ecv,
                                  const float* __restrict__ x,
                                  float* __restrict__ y,
                                  const float* __restrict__ user_emb,
                                  const float* __restrict__ item_id,
                                  float* __restrict__ out) {
    int b = blockIdx.x;
    int tid = threadIdx.x;
    if (b < SPMM_BLOCKS) {
        int g = b * 256 + tid;
        int row = g >> 4;
        int lane = g & 15;
        if (row >= NTOT) return;
        float4 a = spmm_row(rp, ecv, reinterpret_cast<const float4*>(x), row, lane);
        reinterpret_cast<float4*>(y)[(size_t)row * 16 + lane] = a;
        return;
    }
    b -= SPMM_BLOCKS;
    int idx = b * 256 + tid;
    if (idx >= ECHO4) return;
    float4 v = (idx < UD4)
             ? reinterpret_cast<const float4*>(user_emb)[idx]
             : reinterpret_cast<const float4*>(item_id)[idx - UD4];
    reinterpret_cast<float4*>(out)[ND4 + idx] = v;
}

// Layer 2: y2 = spmm(y1). Pure.
__global__ void spmm_mid_kernel(const int* __restrict__ rp,
                                const int2* __restrict__ ecv,
                                const float* __restrict__ x,
                                float* __restrict__ y) {
    int g = blockIdx.x * blockDim.x + threadIdx.x;
    int row = g >> 4;
    int lane = g & 15;
    if (row >= NTOT) return;
    float4 a = spmm_row(rp, ecv, reinterpret_cast<const float4*>(x), row, lane);
    reinterpret_cast<float4*>(y)[(size_t)row * 16 + lane] = a;
}

// Layer 3 fused finalize: out = (A + B + C + spmm(C)) * 0.25
__global__ void spmm_last_kernel(const int* __restrict__ rp,
                                 const int2* __restrict__ ecv,
                                 const float* __restrict__ A,
                                 const float* __restrict__ B,
                                 const float* __restrict__ C,
                                 float* __restrict__ out) {
    int g = blockIdx.x * blockDim.x + threadIdx.x;
    int row = g >> 4;
    int lane = g & 15;
    if (row >= NTOT) return;
    float4 a = spmm_row(rp, ecv, reinterpret_cast<const float4*>(C), row, lane);
    size_t o = (size_t)row * 16 + lane;
    float4 va = reinterpret_cast<const float4*>(A)[o];
    float4 vb = reinterpret_cast<const float4*>(B)[o];
    float4 vc = reinterpret_cast<const float4*>(C)[o];
    reinterpret_cast<float4*>(out)[o] = make_float4(
        (va.x + vb.x + vc.x + a.x) * 0.25f,
        (va.y + vb.y + vc.y + a.y) * 0.25f,
        (va.z + vb.z + vc.z + a.z) * 0.25f,
        (va.w + vb.w + vc.w + a.w) * 0.25f);
}

// ---------------------------------------------------------------------------
extern "C" void kernel_launch(void* const* d_in, const int* in_sizes, int n_in,
                              void* d_out, int out_size) {
    const int*   edge_row = (const int*)  d_in[0];
    const int*   edge_col = (const int*)  d_in[1];
    const float* edge_val = (const float*)d_in[2];
    const float* user_emb = (const float*)d_in[3];
    const float* item_id  = (const float*)d_in[4];
    const float* brand    = (const float*)d_in[5];
    const float* content  = (const float*)d_in[6];
    const float* fusion_W = (const float*)d_in[7];
    const float* fusion_b = (const float*)d_in[8];
    const int E = in_sizes[0];

    float *A, *B, *C;
    int *rp, *cur, *bsum;
    int2 *ecv;
    cudaGetSymbolAddress((void**)&A,    g_bufA);
    cudaGetSymbolAddress((void**)&B,    g_bufB);
    cudaGetSymbolAddress((void**)&C,    g_bufC);
    cudaGetSymbolAddress((void**)&rp,   g_rowptr);
    cudaGetSymbolAddress((void**)&cur,  g_cursor);
    cudaGetSymbolAddress((void**)&ecv,  g_ecv);
    cudaGetSymbolAddress((void**)&bsum, g_bsum);

    cudaMemsetAsync(cur, 0, NTOT * sizeof(int));

    // K1: GEMM + hist + user/brand init (wave-overlapped)
    int histBlocks = ((E + 3) / 4 + 255) / 256;
    int initBlocks = (INIT4 + 255) / 256;
    mega1_kernel<<<GEMM_BLOCKS + histBlocks + initBlocks, 256>>>(
        item_id, content, fusion_W, fusion_b, user_emb, brand,
        edge_row, E, histBlocks, cur, A);

    // CSR: partial sums -> fused bsum-scan + rowptr -> scatter
    scan_partial_kernel<<<SCAN_NBLK, 256>>>(cur, bsum);
    write_rowptr_kernel<<<SCAN_NBLK, 256>>>(cur, bsum, rp, cur, E);
    scatter_kernel<<<((E + 3) / 4 + 255) / 256, 256>>>(
        edge_row, edge_col, edge_val, E, cur, (long long*)ecv);

    // Propagation: A -> B -> C -> fused last layer + finalize
    spmm1_mega_kernel<<<SPMM_BLOCKS + ECHO_BLOCKS, 256>>>(
        rp, ecv, A, B, user_emb, item_id, (float*)d_out);
    spmm_mid_kernel<<<SPMM_BLOCKS, 256>>>(rp, ecv, B, C);
    spmm_last_kernel<<<SPMM_BLOCKS, 256>>>(rp, ecv, A, B, C, (float*)d_out);
}